// round 1
// baseline (speedup 1.0000x reference)
#include <cuda_runtime.h>

// Problem shape (fixed by setup_inputs)
#define B_  256
#define T_  8192
#define TB  256          // timesteps per block
#define NTH 256          // threads per block

// Illegal transition bitmask: pairs (0,2),(1,0),(2,0),(2,1) -> codes 2,3,6,7
#define ILLEGAL_MASK 0xCC

struct Acc {
    double robot, phase, csum, ccnt, speed, vel, acc;
};
__device__ Acc g_acc;

__global__ void zero_kernel() {
    g_acc.robot = 0.0; g_acc.phase = 0.0; g_acc.csum = 0.0; g_acc.ccnt = 0.0;
    g_acc.speed = 0.0; g_acc.vel = 0.0;   g_acc.acc  = 0.0;
}

__device__ __forceinline__ float warp_sum(float v) {
    #pragma unroll
    for (int o = 16; o; o >>= 1) v += __shfl_down_sync(0xffffffffu, v, o);
    return v;
}

__global__ __launch_bounds__(NTH)
void loss_kernel(const float* __restrict__ pred_robot,
                 const float* __restrict__ pred_phase,
                 const float* __restrict__ gt_robot,
                 const int*   __restrict__ gt_phase)
{
    // Robot rows padded to 13 floats: stride 13 is coprime with 32 banks -> no conflicts.
    __shared__ float shR[(TB + 2) * 13];      // 13416 B
    __shared__ float shP[(TB + 1) * 3];       //  3084 B
    __shared__ float sred[7][8];

    const int b   = blockIdx.y;
    const int t0  = blockIdx.x * TB;
    const int tid = threadIdx.x;

    float racc = 0.f, pacc = 0.f, cacc = 0.f, ccnt = 0.f;
    float sacc = 0.f, vacc = 0.f, aacc = 0.f;

    // ---- Cooperative staged load of robot chunk (+2 halo rows), fusing robot MSE ----
    {
        const long base  = ((long)b * T_ + t0) * 12;   // 48B-aligned (12 floats)
        const int  nRows = min(TB + 2, T_ - t0);
        const int  nF4   = nRows * 3;                  // 3 float4 per 12-float row
        const float4* p4 = (const float4*)(pred_robot + base);
        const float4* g4 = (const float4*)(gt_robot   + base);
        for (int j = tid; j < nF4; j += NTH) {
            float4 p = p4[j];
            int row  = j / 3;
            int s    = row * 13 + (j - row * 3) * 4;
            shR[s] = p.x; shR[s + 1] = p.y; shR[s + 2] = p.z; shR[s + 3] = p.w;
            if (row < TB) {   // halo rows belong to the next block's main range
                float4 g = g4[j];
                float dx = p.x - g.x, dy = p.y - g.y, dz = p.z - g.z, dw = p.w - g.w;
                racc += dx * dx + dy * dy + dz * dz + dw * dw;
            }
        }
    }
    // ---- Stage phase chunk (+1 halo row) ----
    {
        const long pbase = ((long)b * T_ + t0) * 3;
        const int  nP    = min(TB + 1, T_ - t0) * 3;
        const float* ph  = pred_phase + pbase;
        for (int j = tid; j < nP; j += NTH) shP[j] = ph[j];
    }
    __syncthreads();

    const int t = t0 + tid;   // chunks tile T exactly; t < T always

    // ---- Phase NLL (log_softmax over 3 classes) ----
    {
        float l0 = shP[tid * 3], l1 = shP[tid * 3 + 1], l2 = shP[tid * 3 + 2];
        float m   = fmaxf(l0, fmaxf(l1, l2));
        float lse = m + logf(expf(l0 - m) + expf(l1 - m) + expf(l2 - m));
        int   gp  = gt_phase[(long)b * T_ + t];
        float lg  = (gp == 0) ? l0 : ((gp == 1) ? l1 : l2);
        pacc = lse - lg;

        // argmax at t (first-max tie-break, matches jnp.argmax)
        int pt = 0; float bm = l0;
        if (l1 > bm) { bm = l1; pt = 1; }
        if (l2 > bm) { pt = 2; }

        // ---- Coherence: illegal (argmax_t -> argmax_{t+1}) transitions ----
        if (t + 1 < T_) {
            float n0 = shP[tid * 3 + 3], n1 = shP[tid * 3 + 4], n2 = shP[tid * 3 + 5];
            int pt1 = 0; float sel = n0;
            if (n1 > sel) { sel = n1; pt1 = 1; }
            if (n2 > sel) { sel = n2; pt1 = 2; }
            int code = pt * 3 + pt1;
            if ((ILLEGAL_MASK >> code) & 1) { cacc = sel * sel; ccnt = 1.0f; }
        }
    }

    // ---- Temporal robot terms: vel / speed-penalty / acc ----
    {
        const int s0 = tid * 13;
        float r0[12], r1[12];
        #pragma unroll
        for (int d = 0; d < 12; d++) r0[d] = shR[s0 + d];
        if (t + 1 < T_) {
            float v[12];
            #pragma unroll
            for (int d = 0; d < 12; d++) {
                r1[d] = shR[s0 + 13 + d];
                v[d]  = r1[d] - r0[d];
                vacc += v[d] * v[d];
            }
            #pragma unroll
            for (int k = 0; k < 4; k++) {
                float sp2 = v[3*k]*v[3*k] + v[3*k+1]*v[3*k+1] + v[3*k+2]*v[3*k+2];
                float pen = fmaxf(sqrtf(sp2) - 10.0f, 0.0f);
                sacc += pen * pen;
            }
            if (t + 2 < T_) {
                #pragma unroll
                for (int d = 0; d < 12; d++) {
                    float a = shR[s0 + 26 + d] - 2.0f * r1[d] + r0[d];
                    aacc += a * a;
                }
            }
        }
    }

    // ---- Block reduction: warp shuffle -> smem -> warp0 -> double atomics ----
    float vals[7] = {racc, pacc, cacc, ccnt, sacc, vacc, aacc};
    const int lane = tid & 31, wid = tid >> 5;
    #pragma unroll
    for (int i = 0; i < 7; i++) {
        float w = warp_sum(vals[i]);
        if (lane == 0) sred[i][wid] = w;
    }
    __syncthreads();
    if (wid == 0) {
        #pragma unroll
        for (int i = 0; i < 7; i++) {
            float w = (lane < 8) ? sred[i][lane] : 0.0f;
            vals[i] = warp_sum(w);
        }
        if (lane == 0) {
            atomicAdd(&g_acc.robot, (double)vals[0]);
            atomicAdd(&g_acc.phase, (double)vals[1]);
            atomicAdd(&g_acc.csum,  (double)vals[2]);
            atomicAdd(&g_acc.ccnt,  (double)vals[3]);
            atomicAdd(&g_acc.speed, (double)vals[4]);
            atomicAdd(&g_acc.vel,   (double)vals[5]);
            atomicAdd(&g_acc.acc,   (double)vals[6]);
        }
    }
}

__global__ void final_kernel(float* __restrict__ out) {
    double robot = g_acc.robot / ((double)B_ * T_ * 12);
    double phase = g_acc.phase / ((double)B_ * T_);
    double coher = (g_acc.ccnt > 0.0) ? (g_acc.csum / g_acc.ccnt) : 0.0;
    double speed = 5.0  * g_acc.speed / ((double)B_ * (T_ - 1) * 4);
    double vel   = 0.05 * g_acc.vel   / ((double)B_ * (T_ - 1) * 12);
    double acc   = 0.01 * g_acc.acc   / ((double)B_ * (T_ - 2) * 12);
    out[0] = (float)(robot + phase + 10.0 * coher + speed + vel + acc);
}

extern "C" void kernel_launch(void* const* d_in, const int* in_sizes, int n_in,
                              void* d_out, int out_size)
{
    const float* pred_robot = (const float*)d_in[0];
    const float* pred_phase = (const float*)d_in[1];
    const float* gt_robot   = (const float*)d_in[2];
    const int*   gt_phase   = (const int*)  d_in[3];

    zero_kernel<<<1, 1>>>();
    dim3 grid(T_ / TB, B_);      // (32, 256) = 8192 blocks
    loss_kernel<<<grid, NTH>>>(pred_robot, pred_phase, gt_robot, gt_phase);
    final_kernel<<<1, 1>>>((float*)d_out);
}

// round 2
// speedup vs baseline: 1.9329x; 1.9329x over previous
#include <cuda_runtime.h>

// Problem shape (fixed by setup_inputs)
#define B_  256
#define T_  8192
#define TB  256          // timesteps per block (T_ % TB == 0)
#define NTH 256          // threads per block
#define NCHUNK (T_ / TB) // 32

// Illegal transition bitmask: pairs (0,2),(1,0),(2,0),(2,1) -> codes 2,3,6,7
#define ILLEGAL_MASK 0xCC

// Zero-initialized at module load; final_kernel resets after each read,
// so every kernel_launch call observes zeros (deterministic, graph-safe).
__device__ double g_main = 0.0;
__device__ double g_csum = 0.0;
__device__ double g_ccnt = 0.0;

__device__ __forceinline__ float warp_sum(float v) {
    #pragma unroll
    for (int o = 16; o; o >>= 1) v += __shfl_down_sync(0xffffffffu, v, o);
    return v;
}

__global__ __launch_bounds__(NTH)
void loss_kernel(const float* __restrict__ pred_robot,
                 const float* __restrict__ pred_phase,
                 const float* __restrict__ gt_robot,
                 const int*   __restrict__ gt_phase)
{
    // Robot rows padded to 13 floats: stride 13 coprime with 32 banks -> conflict-free.
    __shared__ float shR[(TB + 2) * 13];              // 13416 B
    __shared__ __align__(16) float shP[(TB + 1) * 3]; //  3084 B
    __shared__ float sred[3][8];

    const int b    = blockIdx.y;
    const int bx   = blockIdx.x;
    const int t0   = bx * TB;
    const int tid  = threadIdx.x;
    const bool has_halo = (bx < NCHUNK - 1);

    const long rbase = ((long)b * T_ + t0) * 12;
    const long pbase = ((long)b * T_ + t0) * 3;
    const float4* p4 = (const float4*)(pred_robot + rbase);
    const float4* g4 = (const float4*)(gt_robot   + rbase);
    const float4* h4 = (const float4*)(pred_phase + pbase);

    // ---- Issue all independent global loads up front (MLP ~ 8) ----
    float4 p0 = p4[tid];
    float4 p1 = p4[tid + 256];
    float4 p2 = p4[tid + 512];
    float4 g0 = g4[tid];
    float4 g1 = g4[tid + 256];
    float4 g2 = g4[tid + 512];
    float4 ph = (tid < 192) ? h4[tid] : make_float4(0.f, 0.f, 0.f, 0.f);
    const int gp = gt_phase[(long)b * T_ + t0 + tid];
    float4 hr;                         // robot halo: 6 float4 = rows TB, TB+1
    if (has_halo && tid < 6)  hr = p4[768 + tid];
    float  hp0 = 0.f, hp1 = 0.f, hp2 = 0.f;  // phase halo row TB
    if (has_halo && tid == 0) { hp0 = pred_phase[pbase + 768];
                                hp1 = pred_phase[pbase + 769];
                                hp2 = pred_phase[pbase + 770]; }

    // ---- Robot MSE fused into the stream ----
    float racc;
    {
        float dx, dy, dz, dw, s = 0.f;
        dx = p0.x - g0.x; dy = p0.y - g0.y; dz = p0.z - g0.z; dw = p0.w - g0.w;
        s += dx*dx + dy*dy + dz*dz + dw*dw;
        dx = p1.x - g1.x; dy = p1.y - g1.y; dz = p1.z - g1.z; dw = p1.w - g1.w;
        s += dx*dx + dy*dy + dz*dz + dw*dw;
        dx = p2.x - g2.x; dy = p2.y - g2.y; dz = p2.z - g2.z; dw = p2.w - g2.w;
        s += dx*dx + dy*dy + dz*dz + dw*dw;
        racc = s;
    }

    // ---- Store pred_robot to padded smem ----
    {
        int j, row, s;
        j = tid;        row = j / 3; s = row * 13 + (j - row * 3) * 4;
        shR[s] = p0.x; shR[s+1] = p0.y; shR[s+2] = p0.z; shR[s+3] = p0.w;
        j = tid + 256;  row = j / 3; s = row * 13 + (j - row * 3) * 4;
        shR[s] = p1.x; shR[s+1] = p1.y; shR[s+2] = p1.z; shR[s+3] = p1.w;
        j = tid + 512;  row = j / 3; s = row * 13 + (j - row * 3) * 4;
        shR[s] = p2.x; shR[s+1] = p2.y; shR[s+2] = p2.z; shR[s+3] = p2.w;
        if (has_halo && tid < 6) {
            j = 768 + tid; row = j / 3; s = row * 13 + (j - row * 3) * 4;
            shR[s] = hr.x; shR[s+1] = hr.y; shR[s+2] = hr.z; shR[s+3] = hr.w;
        }
    }
    if (tid < 192) ((float4*)shP)[tid] = ph;
    if (has_halo && tid == 0) { shP[768] = hp0; shP[769] = hp1; shP[770] = hp2; }
    __syncthreads();

    const int t = t0 + tid;
    float pacc, cacc = 0.f, ccnt = 0.f;
    float sacc = 0.f, vacc = 0.f, aacc = 0.f;

    // ---- Phase NLL + coherence ----
    {
        float l0 = shP[tid*3], l1 = shP[tid*3+1], l2 = shP[tid*3+2];
        float m   = fmaxf(l0, fmaxf(l1, l2));
        float lse = m + logf(expf(l0 - m) + expf(l1 - m) + expf(l2 - m));
        float lg  = (gp == 0) ? l0 : ((gp == 1) ? l1 : l2);
        pacc = lse - lg;

        int pt = 0; float bm = l0;
        if (l1 > bm) { bm = l1; pt = 1; }
        if (l2 > bm) { pt = 2; }

        if (t + 1 < T_) {
            float n0 = shP[tid*3+3], n1 = shP[tid*3+4], n2 = shP[tid*3+5];
            int pt1 = 0; float sel = n0;
            if (n1 > sel) { sel = n1; pt1 = 1; }
            if (n2 > sel) { pt1 = 2; sel = n2; }
            int code = pt * 3 + pt1;
            if ((ILLEGAL_MASK >> code) & 1) { cacc = sel * sel; ccnt = 1.0f; }
        }
    }

    // ---- Temporal robot terms ----
    {
        const int s0 = tid * 13;
        float r0[12], r1[12];
        #pragma unroll
        for (int d = 0; d < 12; d++) r0[d] = shR[s0 + d];
        if (t + 1 < T_) {
            float v[12];
            #pragma unroll
            for (int d = 0; d < 12; d++) {
                r1[d] = shR[s0 + 13 + d];
                v[d]  = r1[d] - r0[d];
                vacc += v[d] * v[d];
            }
            #pragma unroll
            for (int k = 0; k < 4; k++) {
                float sp2 = v[3*k]*v[3*k] + v[3*k+1]*v[3*k+1] + v[3*k+2]*v[3*k+2];
                float pen = fmaxf(sqrtf(sp2) - 10.0f, 0.0f);
                sacc += pen * pen;
            }
            if (t + 2 < T_) {
                #pragma unroll
                for (int d = 0; d < 12; d++) {
                    float a = shR[s0 + 26 + d] - 2.0f * r1[d] + r0[d];
                    aacc += a * a;
                }
            }
        }
    }

    // ---- Fold 5 constant-normalized terms into one weighted value ----
    const float W_R = 1.0f   / ((float)B_ * T_ * 12);
    const float W_P = 1.0f   / ((float)B_ * T_);
    const float W_S = 5.0f   / ((float)B_ * (T_ - 1) * 4);
    const float W_V = 0.05f  / ((float)B_ * (T_ - 1) * 12);
    const float W_A = 0.01f  / ((float)B_ * (T_ - 2) * 12);
    float wmain = racc * W_R + pacc * W_P + sacc * W_S + vacc * W_V + aacc * W_A;

    // ---- Block reduction: 3 values -> 3 double atomics ----
    float vals[3] = {wmain, cacc, ccnt};
    const int lane = tid & 31, wid = tid >> 5;
    #pragma unroll
    for (int i = 0; i < 3; i++) {
        float w = warp_sum(vals[i]);
        if (lane == 0) sred[i][wid] = w;
    }
    __syncthreads();
    if (wid == 0) {
        #pragma unroll
        for (int i = 0; i < 3; i++) {
            float w = (lane < 8) ? sred[i][lane] : 0.0f;
            vals[i] = warp_sum(w);
        }
        if (lane == 0) {
            atomicAdd(&g_main, (double)vals[0]);
            atomicAdd(&g_csum, (double)vals[1]);
            atomicAdd(&g_ccnt, (double)vals[2]);
        }
    }
}

__global__ void final_kernel(float* __restrict__ out) {
    double coher = (g_ccnt > 0.0) ? (g_csum / g_ccnt) : 0.0;
    out[0] = (float)(g_main + 10.0 * coher);
    // Reset for the next invocation (globals start zero at module load).
    g_main = 0.0; g_csum = 0.0; g_ccnt = 0.0;
}

extern "C" void kernel_launch(void* const* d_in, const int* in_sizes, int n_in,
                              void* d_out, int out_size)
{
    const float* pred_robot = (const float*)d_in[0];
    const float* pred_phase = (const float*)d_in[1];
    const float* gt_robot   = (const float*)d_in[2];
    const int*   gt_phase   = (const int*)  d_in[3];

    dim3 grid(NCHUNK, B_);   // (32, 256) = 8192 blocks
    loss_kernel<<<grid, NTH>>>(pred_robot, pred_phase, gt_robot, gt_phase);
    final_kernel<<<1, 1>>>((float*)d_out);
}